// round 1
// baseline (speedup 1.0000x reference)
#include <cuda_runtime.h>
#include <math.h>

#define WIN   11
#define RAD   5
#define TS    32
#define INW   42              // TS + 2*RAD
#define PIMG  44              // raw tile pitch (floats)
#define PHB   36              // hblur pitch (floats, mult of 4 for float4)
#define NTHREADS 256

#define C1 0.0001f            // 0.01^2
#define C2 0.0009f            // 0.03^2

struct GW { float g[WIN]; };

__device__ double g_accum;

// ---- shared memory layout (floats) ----
// sA: [42][44]   sB: [42][44]   sF: [42][44]
// hb: [8][42][36]  field order: 0=A 1=B 2=F 3=AA 4=BB 5=FF 6=AF 7=BF
// red: [8]
#define OFF_B   (INW * PIMG)
#define OFF_F   (2 * INW * PIMG)
#define OFF_HB  (3 * INW * PIMG)
#define OFF_RED (OFF_HB + 8 * INW * PHB)
#define SMEM_FLOATS (OFF_RED + 8)
#define SMEM_BYTES  (SMEM_FLOATS * 4)

__global__ void zero_accum_kernel() { g_accum = 0.0; }

__device__ __forceinline__ float ssim_val(float mu1, float mu2,
                                          float e11, float e22, float e12) {
    float mu1sq = mu1 * mu1;
    float mu2sq = mu2 * mu2;
    float mu12  = mu1 * mu2;
    float sig1  = e11 - mu1sq;
    float sig2  = e22 - mu2sq;
    float sig12 = e12 - mu12;
    float num = (2.0f * mu12 + C1) * (2.0f * sig12 + C2);
    float den = (mu1sq + mu2sq + C1) * (sig1 + sig2 + C2);
    return __fdividef(num, den);
}

__global__ __launch_bounds__(NTHREADS)
void ssim_tile_kernel(const float* __restrict__ A,
                      const float* __restrict__ B,
                      const float* __restrict__ F,
                      GW gw) {
    extern __shared__ float sm[];
    float* sA  = sm;
    float* sB  = sm + OFF_B;
    float* sF  = sm + OFF_F;
    float* hb  = sm + OFF_HB;
    float* red = sm + OFF_RED;

    const int tid = threadIdx.x;
    const int x0 = blockIdx.x * TS - RAD;
    const int y0 = blockIdx.y * TS - RAD;
    const size_t pbase = (size_t)blockIdx.z * (512 * 512);

    // ---- load 42x42 raw tiles (zero-padded) ----
    #pragma unroll 2
    for (int i = tid; i < INW * INW; i += NTHREADS) {
        int r = i / INW, c = i - r * INW;
        int gx = x0 + c, gy = y0 + r;
        float a = 0.f, b = 0.f, f = 0.f;
        if ((unsigned)gx < 512u && (unsigned)gy < 512u) {
            size_t off = pbase + (size_t)gy * 512 + gx;
            a = A[off]; b = B[off]; f = F[off];
        }
        sA[r * PIMG + c] = a;
        sB[r * PIMG + c] = b;
        sF[r * PIMG + c] = f;
    }
    __syncthreads();

    // ---- horizontal 11-tap pass over 8 fields: 42 rows x 32 cols ----
    for (int i = tid; i < INW * TS; i += NTHREADS) {
        int r = i >> 5;            // / 32
        int c = i & 31;            // % 32
        const float* pa = &sA[r * PIMG + c];
        const float* pb = &sB[r * PIMG + c];
        const float* pf = &sF[r * PIMG + c];
        float wa = 0.f, wb = 0.f, wf = 0.f;
        float waa = 0.f, wbb = 0.f, wff = 0.f, waf = 0.f, wbf = 0.f;
        #pragma unroll
        for (int k = 0; k < WIN; k++) {
            float g = gw.g[k];
            float a = pa[k], b = pb[k], f = pf[k];
            wa  += g * a;       wb  += g * b;       wf  += g * f;
            waa += g * (a * a); wbb += g * (b * b); wff += g * (f * f);
            waf += g * (a * f); wbf += g * (b * f);
        }
        int o = r * PHB + c;
        hb[0 * INW * PHB + o] = wa;
        hb[1 * INW * PHB + o] = wb;
        hb[2 * INW * PHB + o] = wf;
        hb[3 * INW * PHB + o] = waa;
        hb[4 * INW * PHB + o] = wbb;
        hb[5 * INW * PHB + o] = wff;
        hb[6 * INW * PHB + o] = waf;
        hb[7 * INW * PHB + o] = wbf;
    }
    __syncthreads();

    // ---- vertical 11-tap pass: each thread = 1 row, 4 consecutive cols ----
    const int vr = tid >> 3;          // 0..31
    const int vc = (tid & 7) << 2;    // 0,4,...,28
    float4 acc[8];
    #pragma unroll
    for (int f = 0; f < 8; f++) acc[f] = make_float4(0.f, 0.f, 0.f, 0.f);

    #pragma unroll
    for (int k = 0; k < WIN; k++) {
        float g = gw.g[k];
        #pragma unroll
        for (int f = 0; f < 8; f++) {
            const float4 v = *(const float4*)&hb[(f * INW + vr + k) * PHB + vc];
            acc[f].x += g * v.x;
            acc[f].y += g * v.y;
            acc[f].z += g * v.z;
            acc[f].w += g * v.w;
        }
    }

    // ---- SSIM map for both pairs, per lane-of-4 ----
    float local = 0.f;
    {
        const float* mA  = (const float*)&acc[0];
        const float* mB  = (const float*)&acc[1];
        const float* mF  = (const float*)&acc[2];
        const float* eAA = (const float*)&acc[3];
        const float* eBB = (const float*)&acc[4];
        const float* eFF = (const float*)&acc[5];
        const float* eAF = (const float*)&acc[6];
        const float* eBF = (const float*)&acc[7];
        #pragma unroll
        for (int j = 0; j < 4; j++) {
            float s1 = ssim_val(mA[j], mF[j], eAA[j], eFF[j], eAF[j]);
            float s2 = ssim_val(mB[j], mF[j], eBB[j], eFF[j], eBF[j]);
            local += s1 + s2;
        }
    }

    // ---- reduction ----
    #pragma unroll
    for (int o = 16; o > 0; o >>= 1)
        local += __shfl_down_sync(0xffffffffu, local, o);
    if ((tid & 31) == 0) red[tid >> 5] = local;
    __syncthreads();
    if (tid < 8) {
        float v = red[tid];
        #pragma unroll
        for (int o = 4; o > 0; o >>= 1)
            v += __shfl_down_sync(0xffu, v, o);
        if (tid == 0) atomicAdd(&g_accum, (double)v);
    }
}

__global__ void finalize_kernel(float* __restrict__ out) {
    // loss = 0.5*mean(map1) + 0.5*mean(map2) = 0.5 * sum(s1+s2) / Npix
    out[0] = (float)(0.5 * g_accum / 12582912.0);
}

extern "C" void kernel_launch(void* const* d_in, const int* in_sizes, int n_in,
                              void* d_out, int out_size) {
    const float* A = (const float*)d_in[0];
    const float* B = (const float*)d_in[1];
    const float* F = (const float*)d_in[2];

    // Gaussian weights in double, normalized, then cast (matches numpy ref).
    GW gw;
    double gd[WIN], s = 0.0;
    for (int i = 0; i < WIN; i++) {
        double d = (double)(i - RAD);
        gd[i] = exp(-(d * d) / (2.0 * 1.5 * 1.5));
        s += gd[i];
    }
    for (int i = 0; i < WIN; i++) gw.g[i] = (float)(gd[i] / s);

    cudaFuncSetAttribute(ssim_tile_kernel,
                         cudaFuncAttributeMaxDynamicSharedMemorySize, SMEM_BYTES);

    zero_accum_kernel<<<1, 1>>>();
    dim3 grid(512 / TS, 512 / TS, 16 * 3);
    ssim_tile_kernel<<<grid, NTHREADS, SMEM_BYTES>>>(A, B, F, gw);
    finalize_kernel<<<1, 1>>>((float*)d_out);
}